// round 14
// baseline (speedup 1.0000x reference)
#include <cuda_runtime.h>
#include <cuda_bf16.h>
#include <math.h>
#include <stdint.h>

#define D       256
#define SEQ     2048
#define T       16384
#define H       4
#define F       512

typedef __nv_bfloat16 bf16;

// ---------------- scratch (device globals; no allocation allowed) -----------
__device__ bf16   g_xnb [T * D];
__device__ bf16   g_qb  [H * T * D];
__device__ bf16   g_kb  [H * T * D];
__device__ bf16   g_vb  [H * T * D];
__device__ bf16   g_catb[T * H * D];
__device__ float  g_x1  [T * D];
__device__ bf16   g_xn2b[T * D];
__device__ bf16   g_ffb [T * F];
__device__ bf16   g_wtqkv[12 * D * D];
__device__ bf16   g_wto  [D * (H * D)];
__device__ bf16   g_wt1  [F * D];
__device__ bf16   g_wt2  [D * F];

// ---------------- small helpers ----------------------------------------------
__device__ __forceinline__ uint32_t smem_u32(const void* p) {
    uint32_t a;
    asm("{ .reg .u64 t; cvta.to.shared.u64 t, %1; cvt.u32.u64 %0, t; }"
        : "=r"(a) : "l"(p));
    return a;
}
__device__ __forceinline__ void ldsm4(uint32_t* r, uint32_t a) {
    asm volatile("ldmatrix.sync.aligned.m8n8.x4.shared.b16 {%0,%1,%2,%3}, [%4];"
        : "=r"(r[0]), "=r"(r[1]), "=r"(r[2]), "=r"(r[3]) : "r"(a));
}
__device__ __forceinline__ void ldsm4t(uint32_t* r, uint32_t a) {
    asm volatile("ldmatrix.sync.aligned.m8n8.x4.trans.shared.b16 {%0,%1,%2,%3}, [%4];"
        : "=r"(r[0]), "=r"(r[1]), "=r"(r[2]), "=r"(r[3]) : "r"(a));
}
__device__ __forceinline__ void hmma(float* d, const uint32_t* a, uint32_t b0, uint32_t b1) {
    asm volatile("mma.sync.aligned.m16n8k16.row.col.f32.bf16.bf16.f32 "
        "{%0,%1,%2,%3}, {%4,%5,%6,%7}, {%8,%9}, {%0,%1,%2,%3};"
        : "+f"(d[0]), "+f"(d[1]), "+f"(d[2]), "+f"(d[3])
        : "r"(a[0]), "r"(a[1]), "r"(a[2]), "r"(a[3]), "r"(b0), "r"(b1));
}
__device__ __forceinline__ uint32_t cvt_bf16x2(float hi, float lo) {
    uint32_t w;
    asm("cvt.rn.bf16x2.f32 %0, %1, %2;" : "=r"(w) : "f"(hi), "f"(lo));
    return w;
}
// hardware EX2 (MUFU) — exp2f without fast-math is a slow precise polynomial
__device__ __forceinline__ float ex2_approx(float x) {
    float r;
    asm("ex2.approx.ftz.f32 %0, %1;" : "=f"(r) : "f"(x));
    return r;
}
__device__ __forceinline__ void cp16(uint32_t dst, const void* src) {
    asm volatile("cp.async.cg.shared.global [%0], [%1], 16;" :: "r"(dst), "l"(src));
}
#define CP_COMMIT() asm volatile("cp.async.commit_group;" ::: "memory")
#define CP_WAIT(n)  asm volatile("cp.async.wait_group %0;" :: "n"(n) : "memory")

// ---------------- LayerNorm body: warp-per-row -> bf16 ------------------------
__device__ __forceinline__ void ln_body(const float* __restrict__ x,
                                        const float* __restrict__ g,
                                        const float* __restrict__ b,
                                        bf16* __restrict__ out, int blk) {
    int w = threadIdx.x >> 5, lane = threadIdx.x & 31;
    int row = blk * 8 + w;
    const float4* xr = (const float4*)(x + (size_t)row * D);
    float4 a0 = xr[lane * 2];
    float4 a1 = xr[lane * 2 + 1];
    float s = a0.x + a0.y + a0.z + a0.w + a1.x + a1.y + a1.z + a1.w;
    #pragma unroll
    for (int o = 16; o > 0; o >>= 1) s += __shfl_xor_sync(0xffffffffu, s, o);
    float mu = s * (1.0f / D);
    float d0[8] = {a0.x - mu, a0.y - mu, a0.z - mu, a0.w - mu,
                   a1.x - mu, a1.y - mu, a1.z - mu, a1.w - mu};
    float vs = 0.f;
    #pragma unroll
    for (int i = 0; i < 8; i++) vs += d0[i] * d0[i];
    #pragma unroll
    for (int o = 16; o > 0; o >>= 1) vs += __shfl_xor_sync(0xffffffffu, vs, o);
    float rs = rsqrtf(vs * (1.0f / D) + 1e-5f);
    float4 g0 = ((const float4*)g)[lane * 2];
    float4 g1 = ((const float4*)g)[lane * 2 + 1];
    float4 b0 = ((const float4*)b)[lane * 2];
    float4 b1 = ((const float4*)b)[lane * 2 + 1];
    float v[8];
    v[0] = d0[0] * rs * g0.x + b0.x; v[1] = d0[1] * rs * g0.y + b0.y;
    v[2] = d0[2] * rs * g0.z + b0.z; v[3] = d0[3] * rs * g0.w + b0.w;
    v[4] = d0[4] * rs * g1.x + b1.x; v[5] = d0[5] * rs * g1.y + b1.y;
    v[6] = d0[6] * rs * g1.z + b1.z; v[7] = d0[7] * rs * g1.w + b1.w;
    uint4 o;
    o.x = cvt_bf16x2(v[1], v[0]); o.y = cvt_bf16x2(v[3], v[2]);
    o.z = cvt_bf16x2(v[5], v[4]); o.w = cvt_bf16x2(v[7], v[6]);
    ((uint4*)(out + (size_t)row * D))[lane] = o;
}

__global__ void ln_kernel(const float* __restrict__ x, const float* __restrict__ g,
                          const float* __restrict__ b, bf16* __restrict__ out) {
    ln_body(x, g, b, out, blockIdx.x);
}

// ---------------- weight transpose+convert body -------------------------------
__device__ __forceinline__ void wconv_body(const float* __restrict__ in,
                                           bf16* __restrict__ out,
                                           int K, int N, int bx, int by) {
    __shared__ float t[32][33];
    int k0 = by * 32, n0 = bx * 32;
    int tx = threadIdx.x & 31, ty = threadIdx.x >> 5;
    #pragma unroll
    for (int i = 0; i < 4; i++)
        t[ty + i * 8][tx] = in[(size_t)(k0 + ty + i * 8) * N + n0 + tx];
    __syncthreads();
    #pragma unroll
    for (int i = 0; i < 4; i++)
        out[(size_t)(n0 + ty + i * 8) * K + k0 + tx] = __float2bfloat16(t[tx][ty + i * 8]);
}

// ---------------- prolog: weight convert + LN1 in one launch ------------------
__global__ void prolog_kernel(const float* __restrict__ Wq, const float* __restrict__ Wk,
                              const float* __restrict__ Wv, const float* __restrict__ Wo,
                              const float* __restrict__ W1, const float* __restrict__ W2,
                              bf16* __restrict__ wtqkv, bf16* __restrict__ wto,
                              bf16* __restrict__ wt1, bf16* __restrict__ wt2,
                              const float* __restrict__ x, const float* __restrict__ g1,
                              const float* __restrict__ be1, bf16* __restrict__ xnb) {
    int z = blockIdx.x;
    if (z < 768) {
        int m = z >> 6, blk = z & 63;
        const float* in = (m < 4 ? Wq : m < 8 ? Wk : Wv) + (size_t)(m & 3) * D * D;
        wconv_body(in, wtqkv + (size_t)m * D * D, D, D, blk & 7, blk >> 3);
    } else if (z < 1024) {
        int blk = z - 768;
        wconv_body(Wo, wto, H * D, D, blk & 7, blk >> 3);
    } else if (z < 1152) {
        int blk = z - 1024;
        wconv_body(W1, wt1, D, F, blk & 15, blk >> 4);
    } else if (z < 1280) {
        int blk = z - 1152;
        wconv_body(W2, wt2, F, D, blk & 7, blk >> 3);
    } else {
        ln_body(x, g1, be1, xnb, z - 1280);
    }
}

// ---------------- HMMA bf16 GEMM, cp.async 3-stage, 1 sync/chunk --------------
#define GSTAGE (128 * 72 * 2)            // bytes per matrix per stage
#define HGEMM_DSMEM (6 * GSTAGE)         // 110592

template<int K>
__device__ __forceinline__ void hgemm_tile(
    const bf16* __restrict__ A, const bf16* __restrict__ Bt,
    const float* __restrict__ bias, const float* __restrict__ res,
    float* __restrict__ Cf, bf16* __restrict__ Cb,
    int N, int m0, int n0, bool relu, float oscale) {

    extern __shared__ __align__(16) char gsm[];
    uint32_t as_b = smem_u32(gsm);
    uint32_t bs_b = as_b + 3 * GSTAGE;

    int tid = threadIdx.x, w = tid >> 5, lane = tid & 31;
    int mi = lane >> 3, l7 = lane & 7;
    int g = lane >> 2, j = lane & 3;
    int mw = (w >> 1) * 32, nw = (w & 1) * 64;

    float acc[2][8][4];
    #pragma unroll
    for (int mt = 0; mt < 2; mt++)
        #pragma unroll
        for (int nt = 0; nt < 8; nt++)
            #pragma unroll
            for (int c = 0; c < 4; c++) acc[mt][nt][c] = 0.f;

    uint32_t a_off = (uint32_t)(((mw + (mi & 1) * 8 + l7) * 72 + (mi >> 1) * 8) * 2);
    uint32_t b_off = (uint32_t)(((nw + (mi >> 1) * 8 + l7) * 72 + (mi & 1) * 8) * 2);

    int row_ld = tid >> 1;
    int c8_ld  = (tid & 1) * 4;
    const bf16* Ag = A  + (size_t)(m0 + row_ld) * K;
    const bf16* Bg = Bt + (size_t)(n0 + row_ld) * K;
    uint32_t s_row = (uint32_t)(row_ld * 144);

    constexpr int NC = K >> 6;

    #pragma unroll
    for (int i = 0; i < 4; i++) {
        cp16(as_b + s_row + (c8_ld + i) * 16, Ag + (c8_ld + i) * 8);
        cp16(bs_b + s_row + (c8_ld + i) * 16, Bg + (c8_ld + i) * 8);
    }
    CP_COMMIT();
    #pragma unroll
    for (int i = 0; i < 4; i++) {
        cp16(as_b + GSTAGE + s_row + (c8_ld + i) * 16, Ag + 64 + (c8_ld + i) * 8);
        cp16(bs_b + GSTAGE + s_row + (c8_ld + i) * 16, Bg + 64 + (c8_ld + i) * 8);
    }
    CP_COMMIT();

    #pragma unroll
    for (int cidx = 0; cidx < NC; cidx++) {
        if (cidx + 1 < NC) { CP_WAIT(1); } else { CP_WAIT(0); }
        __syncthreads();

        if (cidx + 2 < NC) {
            uint32_t st = (uint32_t)((cidx + 2) % 3) * GSTAGE;
            int k0 = (cidx + 2) << 6;
            #pragma unroll
            for (int i = 0; i < 4; i++) {
                cp16(as_b + st + s_row + (c8_ld + i) * 16, Ag + k0 + (c8_ld + i) * 8);
                cp16(bs_b + st + s_row + (c8_ld + i) * 16, Bg + k0 + (c8_ld + i) * 8);
            }
            CP_COMMIT();
        }

        uint32_t st = (uint32_t)(cidx % 3) * GSTAGE;
        uint32_t ab  = as_b + st + a_off;
        uint32_t bb2 = bs_b + st + b_off;
        #pragma unroll
        for (int kk = 0; kk < 4; kk++) {
            uint32_t eoff = (uint32_t)(kk * 32);
            uint32_t a0[4], a1[4];
            ldsm4(a0, ab + eoff);
            ldsm4(a1, ab + eoff + 16u * 144u);
            #pragma unroll
            for (int nt = 0; nt < 8; nt += 2) {
                uint32_t bb[4];
                ldsm4(bb, bb2 + eoff + (uint32_t)(nt * 8 * 144));
                hmma(acc[0][nt],     a0, bb[0], bb[1]);
                hmma(acc[0][nt + 1], a0, bb[2], bb[3]);
                hmma(acc[1][nt],     a1, bb[0], bb[1]);
                hmma(acc[1][nt + 1], a1, bb[2], bb[3]);
            }
        }
    }

    #pragma unroll
    for (int mt = 0; mt < 2; mt++) {
        int r0 = m0 + mw + mt * 16 + g;
        #pragma unroll
        for (int nt = 0; nt < 8; nt++) {
            int c = n0 + nw + nt * 8 + 2 * j;
            float b0 = bias[c], b1 = bias[c + 1];
            float v00 = (acc[mt][nt][0] + b0) * oscale;
            float v01 = (acc[mt][nt][1] + b1) * oscale;
            float v10 = (acc[mt][nt][2] + b0) * oscale;
            float v11 = (acc[mt][nt][3] + b1) * oscale;
            if (relu) {
                v00 = fmaxf(v00, 0.f); v01 = fmaxf(v01, 0.f);
                v10 = fmaxf(v10, 0.f); v11 = fmaxf(v11, 0.f);
            }
            if (res) {
                float2 r_lo = *(const float2*)(res + (size_t)r0 * N + c);
                float2 r_hi = *(const float2*)(res + (size_t)(r0 + 8) * N + c);
                v00 += r_lo.x; v01 += r_lo.y;
                v10 += r_hi.x; v11 += r_hi.y;
            }
            if (Cb) {
                *(uint32_t*)(Cb + (size_t)r0 * N + c)       = cvt_bf16x2(v01, v00);
                *(uint32_t*)(Cb + (size_t)(r0 + 8) * N + c) = cvt_bf16x2(v11, v10);
            } else {
                *(float2*)(Cf + (size_t)r0 * N + c)       = make_float2(v00, v01);
                *(float2*)(Cf + (size_t)(r0 + 8) * N + c) = make_float2(v10, v11);
            }
        }
    }
}

template<int K>
__global__ void __launch_bounds__(256, 2) hgemm_kernel(
    const bf16* __restrict__ A, const bf16* __restrict__ Bt,
    const float* __restrict__ bias, const float* __restrict__ res,
    float* __restrict__ Cf, bf16* __restrict__ Cb,
    int N, int relu, float oscale) {
    hgemm_tile<K>(A, Bt, bias, res, Cf, Cb, N,
                  blockIdx.y * 128, blockIdx.x * 128, relu != 0, oscale);
}

__global__ void __launch_bounds__(256, 2) qkv_hgemm(
    const bf16* __restrict__ A, const bf16* __restrict__ Wt,
    const float* __restrict__ bq, const float* __restrict__ bk,
    const float* __restrict__ bv,
    bf16* __restrict__ q, bf16* __restrict__ k, bf16* __restrict__ v) {
    int z = blockIdx.z;
    int kind = z >> 2, h = z & 3;
    const bf16* Bt    = Wt + (size_t)z * D * D;
    const float* bias = (kind == 0 ? bq : kind == 1 ? bk : bv) + (size_t)h * D;
    bf16* C = (kind == 0 ? q : kind == 1 ? k : v) + (size_t)h * T * D;
    // q pre-scaled by (1/16)*log2(e) so softmax uses hardware EX2 directly
    float oscale = (kind == 0) ? 0.0625f * 1.44269504088896f : 1.0f;
    hgemm_tile<D>(A, Bt, bias, nullptr, nullptr, C, D,
                  blockIdx.y * 128, blockIdx.x * 128, false, oscale);
}

// ===== HMMA flash attention: BQ=64, 4 warps, KV=32/stage, 2 CTAs/SM ==========
// (single barrier per iteration; softmax via hardware ex2.approx)
#define APITCH 264
#define KVR    32
#define KVSTG  (KVR * APITCH * 2)                 // 16896 B per K (or V) stage
#define ATTN_DSMEM ((64 + 4 * KVR) * APITCH * 2)  // 101376 B

__device__ __forceinline__ void cp_kv32(uint32_t kdst, uint32_t vdst,
                                        const bf16* __restrict__ kg,
                                        const bf16* __restrict__ vg, int tid) {
    #pragma unroll
    for (int t = 0; t < 8; t++) {
        int u = tid + t * 128;
        int row = u >> 5, c16 = u & 31;
        uint32_t so = (uint32_t)(row * (APITCH * 2) + c16 * 16);
        size_t go = (size_t)row * D + c16 * 8;
        cp16(kdst + so, kg + go);
        cp16(vdst + so, vg + go);
    }
}

__global__ void __launch_bounds__(128, 2) attn_kernel(
    const bf16* __restrict__ qg, const bf16* __restrict__ kg,
    const bf16* __restrict__ vg, bf16* __restrict__ cat) {

    extern __shared__ __align__(16) char dsm[];
    bf16* Qs = (bf16*)dsm;
    uint32_t qb32 = smem_u32(Qs);
    uint32_t kv0  = qb32 + 64 * APITCH * 2;

    int tid  = threadIdx.x;
    int w    = tid >> 5;
    int lane = tid & 31;
    int g    = lane >> 2;
    int j    = lane & 3;

    int b  = blockIdx.y >> 2, h = blockIdx.y & 3;
    int q0 = blockIdx.x * 64;

    const bf16* Qg  = qg + ((size_t)h * T + (size_t)b * SEQ + q0) * D;
    const bf16* Kg0 = kg + ((size_t)h * T + (size_t)b * SEQ) * D;
    const bf16* Vg0 = vg + ((size_t)h * T + (size_t)b * SEQ) * D;

    cp_kv32(kv0, kv0 + KVSTG, Kg0, Vg0, tid);
    CP_COMMIT();

    #pragma unroll
    for (int t = 0; t < 16; t++) {
        int u   = tid + t * 128;
        int row = u >> 5, c16 = u & 31;
        *(uint4*)(Qs + row * APITCH + c16 * 8) =
            *(const uint4*)(Qg + (size_t)row * D + c16 * 8);
    }

    float oacc[32][4];
    #pragma unroll
    for (int n = 0; n < 32; n++)
        #pragma unroll
        for (int c = 0; c < 4; c++) oacc[n][c] = 0.f;
    float la0 = 0.f, la1 = 0.f;

    int mi = lane >> 3;
    int l7 = lane & 7;
    uint32_t q_base = qb32 + (uint32_t)(((16 * w + (mi & 1) * 8 + l7) * APITCH + (mi >> 1) * 8) * 2);
    uint32_t k_off  = (uint32_t)((((mi >> 1) * 8 + l7) * APITCH + (mi & 1) * 8) * 2);
    uint32_t v_off  = (uint32_t)((((mi & 1) * 8 + l7) * APITCH + (mi >> 1) * 8) * 2);

    for (int it = 0; it < 64; it++) {
        CP_WAIT(0);
        __syncthreads();

        if (it + 1 < 64) {
            uint32_t st = kv0 + (uint32_t)((it + 1) & 1) * (2 * KVSTG);
            cp_kv32(st, st + KVSTG,
                    Kg0 + (size_t)(it + 1) * KVR * D,
                    Vg0 + (size_t)(it + 1) * KVR * D, tid);
            CP_COMMIT();
        }

        uint32_t kb = kv0 + (uint32_t)(it & 1) * (2 * KVSTG);
        uint32_t vb = kb + KVSTG;

        float sacc[4][4];
        #pragma unroll
        for (int n = 0; n < 4; n++)
            #pragma unroll
            for (int c = 0; c < 4; c++) sacc[n][c] = 0.f;

        #pragma unroll
        for (int kk = 0; kk < 16; kk++) {
            uint32_t eoff = (uint32_t)(kk * 32);
            uint32_t a[4];
            ldsm4(a, q_base + eoff);
            #pragma unroll
            for (int nt = 0; nt < 4; nt += 2) {
                uint32_t bbr[4];
                ldsm4(bbr, kb + k_off + eoff + (uint32_t)(nt * 8 * APITCH * 2));
                hmma(sacc[nt],     a, bbr[0], bbr[1]);
                hmma(sacc[nt + 1], a, bbr[2], bbr[3]);
            }
        }

        uint32_t pf[2][4];
        #pragma unroll
        for (int nt = 0; nt < 4; nt++) {
            float p0 = ex2_approx(fminf(sacc[nt][0], 115.f));
            float p1 = ex2_approx(fminf(sacc[nt][1], 115.f));
            float p2 = ex2_approx(fminf(sacc[nt][2], 115.f));
            float p3 = ex2_approx(fminf(sacc[nt][3], 115.f));
            la0 += p0 + p1;
            la1 += p2 + p3;
            int kt = nt >> 1, sub = nt & 1;
            pf[kt][2 * sub + 0] = cvt_bf16x2(p1, p0);
            pf[kt][2 * sub + 1] = cvt_bf16x2(p3, p2);
        }

        #pragma unroll
        for (int kt = 0; kt < 2; kt++) {
            uint32_t vra = vb + v_off + (uint32_t)(kt * 16 * APITCH * 2);
            #pragma unroll
            for (int nt = 0; nt < 32; nt += 2) {
                uint32_t bbr[4];
                ldsm4t(bbr, vra + (uint32_t)(nt * 8 * 2));
                hmma(oacc[nt],     pf[kt], bbr[0], bbr[1]);
                hmma(oacc[nt + 1], pf[kt], bbr[2], bbr[3]);
            }
        }
    }

    la0 += __shfl_xor_sync(0xffffffffu, la0, 1);
    la0 += __shfl_xor_sync(0xffffffffu, la0, 2);
    la1 += __shfl_xor_sync(0xffffffffu, la1, 1);
    la1 += __shfl_xor_sync(0xffffffffu, la1, 2);
    float inv0 = 1.f / la0;
    float inv1 = 1.f / la1;

    int row_lo = q0 + 16 * w + g;
    bf16* o_lo = cat + ((size_t)(b * SEQ + row_lo)) * (H * D) + h * D;
    bf16* o_hi = o_lo + 8 * (size_t)(H * D);
    #pragma unroll
    for (int nt = 0; nt < 32; nt++) {
        *(uint32_t*)(o_lo + nt * 8 + 2 * j) =
            cvt_bf16x2(oacc[nt][1] * inv0, oacc[nt][0] * inv0);
        *(uint32_t*)(o_hi + nt * 8 + 2 * j) =
            cvt_bf16x2(oacc[nt][3] * inv1, oacc[nt][2] * inv1);
    }
}

// ---------------- launch --------------------------------------------------
extern "C" void kernel_launch(void* const* d_in, const int* in_sizes, int n_in,
                              void* d_out, int out_size) {
    const float* x   = (const float*)d_in[0];
    const float* Wq  = (const float*)d_in[1];
    const float* bq  = (const float*)d_in[2];
    const float* Wk  = (const float*)d_in[3];
    const float* bk  = (const float*)d_in[4];
    const float* Wv  = (const float*)d_in[5];
    const float* bv  = (const float*)d_in[6];
    const float* Wo  = (const float*)d_in[7];
    const float* bo  = (const float*)d_in[8];
    const float* g1  = (const float*)d_in[9];
    const float* be1 = (const float*)d_in[10];
    const float* g2  = (const float*)d_in[11];
    const float* be2 = (const float*)d_in[12];
    const float* W1  = (const float*)d_in[13];
    const float* bf1 = (const float*)d_in[14];
    const float* W2  = (const float*)d_in[15];
    const float* bf2 = (const float*)d_in[16];
    float* out = (float*)d_out;

    bf16 *xnb, *qb, *kb, *vb, *catb, *xn2b, *ffb, *wtqkv, *wto, *wt1, *wt2;
    float *x1;
    cudaGetSymbolAddress((void**)&xnb,   g_xnb);
    cudaGetSymbolAddress((void**)&qb,    g_qb);
    cudaGetSymbolAddress((void**)&kb,    g_kb);
    cudaGetSymbolAddress((void**)&vb,    g_vb);
    cudaGetSymbolAddress((void**)&catb,  g_catb);
    cudaGetSymbolAddress((void**)&x1,    g_x1);
    cudaGetSymbolAddress((void**)&xn2b,  g_xn2b);
    cudaGetSymbolAddress((void**)&ffb,   g_ffb);
    cudaGetSymbolAddress((void**)&wtqkv, g_wtqkv);
    cudaGetSymbolAddress((void**)&wto,   g_wto);
    cudaGetSymbolAddress((void**)&wt1,   g_wt1);
    cudaGetSymbolAddress((void**)&wt2,   g_wt2);

    cudaFuncSetAttribute(attn_kernel, cudaFuncAttributeMaxDynamicSharedMemorySize,
                         ATTN_DSMEM);
    cudaFuncSetAttribute(hgemm_kernel<1024>, cudaFuncAttributeMaxDynamicSharedMemorySize,
                         HGEMM_DSMEM);
    cudaFuncSetAttribute(hgemm_kernel<512>, cudaFuncAttributeMaxDynamicSharedMemorySize,
                         HGEMM_DSMEM);
    cudaFuncSetAttribute(hgemm_kernel<256>, cudaFuncAttributeMaxDynamicSharedMemorySize,
                         HGEMM_DSMEM);
    cudaFuncSetAttribute(qkv_hgemm, cudaFuncAttributeMaxDynamicSharedMemorySize,
                         HGEMM_DSMEM);

    // 0) weight convert+transpose + LN1, single launch
    prolog_kernel<<<1280 + T / 8, 256>>>(Wq, Wk, Wv, Wo, W1, W2,
                                         wtqkv, wto, wt1, wt2,
                                         x, g1, be1, xnb);
    // 1) QKV projections (HMMA 3-stage 1-sync, 2 CTAs/SM)
    qkv_hgemm<<<dim3(2, 128, 12), 256, HGEMM_DSMEM>>>(xnb, wtqkv, bq, bk, bv, qb, kb, vb);
    // 2) HMMA flash attention (BQ=64, 2 CTAs/SM, 1 sync/iter, hw ex2) -> concat bf16
    attn_kernel<<<dim3(32, 32), 128, ATTN_DSMEM>>>(qb, kb, vb, catb);
    // 3) output projection + residual (fp32 out)
    hgemm_kernel<1024><<<dim3(2, 128), 256, HGEMM_DSMEM>>>(catb, wto, bo, x, x1, nullptr,
                                                           D, 0, 1.0f);
    // 4) LN2 -> bf16
    ln_kernel<<<T / 8, 256>>>(x1, g2, be2, xn2b);
    // 5) FFN up + relu -> bf16
    hgemm_kernel<256><<<dim3(4, 128), 256, HGEMM_DSMEM>>>(xn2b, wt1, bf1, nullptr, nullptr, ffb,
                                                          F, 1, 1.0f);
    // 6) FFN down + residual -> output fp32
    hgemm_kernel<512><<<dim3(2, 128), 256, HGEMM_DSMEM>>>(ffb, wt2, bf2, x1, out, nullptr,
                                                          D, 0, 1.0f);
}

// round 15
// speedup vs baseline: 1.0682x; 1.0682x over previous
#include <cuda_runtime.h>
#include <cuda_bf16.h>
#include <math.h>
#include <stdint.h>

#define D       256
#define SEQ     2048
#define T       16384
#define H       4
#define F       512

typedef __nv_bfloat16 bf16;

// ---------------- scratch (device globals; no allocation allowed) -----------
__device__ bf16   g_xnb [T * D];
__device__ bf16   g_qb  [H * T * D];
__device__ bf16   g_kb  [H * T * D];
__device__ bf16   g_vb  [H * T * D];
__device__ bf16   g_catb[T * H * D];
__device__ float  g_x1  [T * D];
__device__ bf16   g_xn2b[T * D];
__device__ bf16   g_ffb [T * F];
__device__ bf16   g_wtqkv[12 * D * D];
__device__ bf16   g_wto  [D * (H * D)];
__device__ bf16   g_wt1  [F * D];
__device__ bf16   g_wt2  [D * F];

// ---------------- small helpers ----------------------------------------------
__device__ __forceinline__ uint32_t smem_u32(const void* p) {
    uint32_t a;
    asm("{ .reg .u64 t; cvta.to.shared.u64 t, %1; cvt.u32.u64 %0, t; }"
        : "=r"(a) : "l"(p));
    return a;
}
__device__ __forceinline__ void ldsm4(uint32_t* r, uint32_t a) {
    asm volatile("ldmatrix.sync.aligned.m8n8.x4.shared.b16 {%0,%1,%2,%3}, [%4];"
        : "=r"(r[0]), "=r"(r[1]), "=r"(r[2]), "=r"(r[3]) : "r"(a));
}
__device__ __forceinline__ void ldsm4t(uint32_t* r, uint32_t a) {
    asm volatile("ldmatrix.sync.aligned.m8n8.x4.trans.shared.b16 {%0,%1,%2,%3}, [%4];"
        : "=r"(r[0]), "=r"(r[1]), "=r"(r[2]), "=r"(r[3]) : "r"(a));
}
__device__ __forceinline__ void hmma(float* d, const uint32_t* a, uint32_t b0, uint32_t b1) {
    asm volatile("mma.sync.aligned.m16n8k16.row.col.f32.bf16.bf16.f32 "
        "{%0,%1,%2,%3}, {%4,%5,%6,%7}, {%8,%9}, {%0,%1,%2,%3};"
        : "+f"(d[0]), "+f"(d[1]), "+f"(d[2]), "+f"(d[3])
        : "r"(a[0]), "r"(a[1]), "r"(a[2]), "r"(a[3]), "r"(b0), "r"(b1));
}
__device__ __forceinline__ uint32_t cvt_bf16x2(float hi, float lo) {
    uint32_t w;
    asm("cvt.rn.bf16x2.f32 %0, %1, %2;" : "=r"(w) : "f"(hi), "f"(lo));
    return w;
}
__device__ __forceinline__ void cp16(uint32_t dst, const void* src) {
    asm volatile("cp.async.cg.shared.global [%0], [%1], 16;" :: "r"(dst), "l"(src));
}
#define CP_COMMIT() asm volatile("cp.async.commit_group;" ::: "memory")
#define CP_WAIT(n)  asm volatile("cp.async.wait_group %0;" :: "n"(n) : "memory")

// ---------------- LayerNorm body: warp-per-row -> bf16 ------------------------
__device__ __forceinline__ void ln_body(const float* __restrict__ x,
                                        const float* __restrict__ g,
                                        const float* __restrict__ b,
                                        bf16* __restrict__ out, int blk) {
    int w = threadIdx.x >> 5, lane = threadIdx.x & 31;
    int row = blk * 8 + w;
    const float4* xr = (const float4*)(x + (size_t)row * D);
    float4 a0 = xr[lane * 2];
    float4 a1 = xr[lane * 2 + 1];
    float s = a0.x + a0.y + a0.z + a0.w + a1.x + a1.y + a1.z + a1.w;
    #pragma unroll
    for (int o = 16; o > 0; o >>= 1) s += __shfl_xor_sync(0xffffffffu, s, o);
    float mu = s * (1.0f / D);
    float d0[8] = {a0.x - mu, a0.y - mu, a0.z - mu, a0.w - mu,
                   a1.x - mu, a1.y - mu, a1.z - mu, a1.w - mu};
    float vs = 0.f;
    #pragma unroll
    for (int i = 0; i < 8; i++) vs += d0[i] * d0[i];
    #pragma unroll
    for (int o = 16; o > 0; o >>= 1) vs += __shfl_xor_sync(0xffffffffu, vs, o);
    float rs = rsqrtf(vs * (1.0f / D) + 1e-5f);
    float4 g0 = ((const float4*)g)[lane * 2];
    float4 g1 = ((const float4*)g)[lane * 2 + 1];
    float4 b0 = ((const float4*)b)[lane * 2];
    float4 b1 = ((const float4*)b)[lane * 2 + 1];
    float v[8];
    v[0] = d0[0] * rs * g0.x + b0.x; v[1] = d0[1] * rs * g0.y + b0.y;
    v[2] = d0[2] * rs * g0.z + b0.z; v[3] = d0[3] * rs * g0.w + b0.w;
    v[4] = d0[4] * rs * g1.x + b1.x; v[5] = d0[5] * rs * g1.y + b1.y;
    v[6] = d0[6] * rs * g1.z + b1.z; v[7] = d0[7] * rs * g1.w + b1.w;
    uint4 o;
    o.x = cvt_bf16x2(v[1], v[0]); o.y = cvt_bf16x2(v[3], v[2]);
    o.z = cvt_bf16x2(v[5], v[4]); o.w = cvt_bf16x2(v[7], v[6]);
    ((uint4*)(out + (size_t)row * D))[lane] = o;
}

__global__ void ln_kernel(const float* __restrict__ x, const float* __restrict__ g,
                          const float* __restrict__ b, bf16* __restrict__ out) {
    ln_body(x, g, b, out, blockIdx.x);
}

// ---------------- weight transpose+convert body -------------------------------
__device__ __forceinline__ void wconv_body(const float* __restrict__ in,
                                           bf16* __restrict__ out,
                                           int K, int N, int bx, int by) {
    __shared__ float t[32][33];
    int k0 = by * 32, n0 = bx * 32;
    int tx = threadIdx.x & 31, ty = threadIdx.x >> 5;
    #pragma unroll
    for (int i = 0; i < 4; i++)
        t[ty + i * 8][tx] = in[(size_t)(k0 + ty + i * 8) * N + n0 + tx];
    __syncthreads();
    #pragma unroll
    for (int i = 0; i < 4; i++)
        out[(size_t)(n0 + ty + i * 8) * K + k0 + tx] = __float2bfloat16(t[tx][ty + i * 8]);
}

// ---------------- prolog: weight convert + LN1 in one launch ------------------
__global__ void prolog_kernel(const float* __restrict__ Wq, const float* __restrict__ Wk,
                              const float* __restrict__ Wv, const float* __restrict__ Wo,
                              const float* __restrict__ W1, const float* __restrict__ W2,
                              bf16* __restrict__ wtqkv, bf16* __restrict__ wto,
                              bf16* __restrict__ wt1, bf16* __restrict__ wt2,
                              const float* __restrict__ x, const float* __restrict__ g1,
                              const float* __restrict__ be1, bf16* __restrict__ xnb) {
    int z = blockIdx.x;
    if (z < 768) {
        int m = z >> 6, blk = z & 63;
        const float* in = (m < 4 ? Wq : m < 8 ? Wk : Wv) + (size_t)(m & 3) * D * D;
        wconv_body(in, wtqkv + (size_t)m * D * D, D, D, blk & 7, blk >> 3);
    } else if (z < 1024) {
        int blk = z - 768;
        wconv_body(Wo, wto, H * D, D, blk & 7, blk >> 3);
    } else if (z < 1152) {
        int blk = z - 1024;
        wconv_body(W1, wt1, D, F, blk & 15, blk >> 4);
    } else if (z < 1280) {
        int blk = z - 1152;
        wconv_body(W2, wt2, F, D, blk & 7, blk >> 3);
    } else {
        ln_body(x, g1, be1, xnb, z - 1280);
    }
}

// ---------------- HMMA bf16 GEMM, cp.async 3-stage, 1 sync/chunk --------------
#define GSTAGE (128 * 72 * 2)            // bytes per matrix per stage
#define HGEMM_DSMEM (6 * GSTAGE)         // 110592

template<int K>
__device__ __forceinline__ void hgemm_tile(
    const bf16* __restrict__ A, const bf16* __restrict__ Bt,
    const float* __restrict__ bias, const float* __restrict__ res,
    float* __restrict__ Cf, bf16* __restrict__ Cb,
    int N, int m0, int n0, bool relu, float oscale) {

    extern __shared__ __align__(16) char gsm[];
    uint32_t as_b = smem_u32(gsm);
    uint32_t bs_b = as_b + 3 * GSTAGE;

    int tid = threadIdx.x, w = tid >> 5, lane = tid & 31;
    int mi = lane >> 3, l7 = lane & 7;
    int g = lane >> 2, j = lane & 3;
    int mw = (w >> 1) * 32, nw = (w & 1) * 64;

    float acc[2][8][4];
    #pragma unroll
    for (int mt = 0; mt < 2; mt++)
        #pragma unroll
        for (int nt = 0; nt < 8; nt++)
            #pragma unroll
            for (int c = 0; c < 4; c++) acc[mt][nt][c] = 0.f;

    uint32_t a_off = (uint32_t)(((mw + (mi & 1) * 8 + l7) * 72 + (mi >> 1) * 8) * 2);
    uint32_t b_off = (uint32_t)(((nw + (mi >> 1) * 8 + l7) * 72 + (mi & 1) * 8) * 2);

    int row_ld = tid >> 1;
    int c8_ld  = (tid & 1) * 4;
    const bf16* Ag = A  + (size_t)(m0 + row_ld) * K;
    const bf16* Bg = Bt + (size_t)(n0 + row_ld) * K;
    uint32_t s_row = (uint32_t)(row_ld * 144);

    constexpr int NC = K >> 6;

    #pragma unroll
    for (int i = 0; i < 4; i++) {
        cp16(as_b + s_row + (c8_ld + i) * 16, Ag + (c8_ld + i) * 8);
        cp16(bs_b + s_row + (c8_ld + i) * 16, Bg + (c8_ld + i) * 8);
    }
    CP_COMMIT();
    #pragma unroll
    for (int i = 0; i < 4; i++) {
        cp16(as_b + GSTAGE + s_row + (c8_ld + i) * 16, Ag + 64 + (c8_ld + i) * 8);
        cp16(bs_b + GSTAGE + s_row + (c8_ld + i) * 16, Bg + 64 + (c8_ld + i) * 8);
    }
    CP_COMMIT();

    #pragma unroll
    for (int cidx = 0; cidx < NC; cidx++) {
        if (cidx + 1 < NC) { CP_WAIT(1); } else { CP_WAIT(0); }
        __syncthreads();

        if (cidx + 2 < NC) {
            uint32_t st = (uint32_t)((cidx + 2) % 3) * GSTAGE;
            int k0 = (cidx + 2) << 6;
            #pragma unroll
            for (int i = 0; i < 4; i++) {
                cp16(as_b + st + s_row + (c8_ld + i) * 16, Ag + k0 + (c8_ld + i) * 8);
                cp16(bs_b + st + s_row + (c8_ld + i) * 16, Bg + k0 + (c8_ld + i) * 8);
            }
            CP_COMMIT();
        }

        uint32_t st = (uint32_t)(cidx % 3) * GSTAGE;
        uint32_t ab  = as_b + st + a_off;
        uint32_t bb2 = bs_b + st + b_off;
        #pragma unroll
        for (int kk = 0; kk < 4; kk++) {
            uint32_t eoff = (uint32_t)(kk * 32);
            uint32_t a0[4], a1[4];
            ldsm4(a0, ab + eoff);
            ldsm4(a1, ab + eoff + 16u * 144u);
            #pragma unroll
            for (int nt = 0; nt < 8; nt += 2) {
                uint32_t bb[4];
                ldsm4(bb, bb2 + eoff + (uint32_t)(nt * 8 * 144));
                hmma(acc[0][nt],     a0, bb[0], bb[1]);
                hmma(acc[0][nt + 1], a0, bb[2], bb[3]);
                hmma(acc[1][nt],     a1, bb[0], bb[1]);
                hmma(acc[1][nt + 1], a1, bb[2], bb[3]);
            }
        }
    }

    #pragma unroll
    for (int mt = 0; mt < 2; mt++) {
        int r0 = m0 + mw + mt * 16 + g;
        #pragma unroll
        for (int nt = 0; nt < 8; nt++) {
            int c = n0 + nw + nt * 8 + 2 * j;
            float b0 = bias[c], b1 = bias[c + 1];
            float v00 = (acc[mt][nt][0] + b0) * oscale;
            float v01 = (acc[mt][nt][1] + b1) * oscale;
            float v10 = (acc[mt][nt][2] + b0) * oscale;
            float v11 = (acc[mt][nt][3] + b1) * oscale;
            if (relu) {
                v00 = fmaxf(v00, 0.f); v01 = fmaxf(v01, 0.f);
                v10 = fmaxf(v10, 0.f); v11 = fmaxf(v11, 0.f);
            }
            if (res) {
                float2 r_lo = *(const float2*)(res + (size_t)r0 * N + c);
                float2 r_hi = *(const float2*)(res + (size_t)(r0 + 8) * N + c);
                v00 += r_lo.x; v01 += r_lo.y;
                v10 += r_hi.x; v11 += r_hi.y;
            }
            if (Cb) {
                *(uint32_t*)(Cb + (size_t)r0 * N + c)       = cvt_bf16x2(v01, v00);
                *(uint32_t*)(Cb + (size_t)(r0 + 8) * N + c) = cvt_bf16x2(v11, v10);
            } else {
                *(float2*)(Cf + (size_t)r0 * N + c)       = make_float2(v00, v01);
                *(float2*)(Cf + (size_t)(r0 + 8) * N + c) = make_float2(v10, v11);
            }
        }
    }
}

template<int K>
__global__ void __launch_bounds__(256, 2) hgemm_kernel(
    const bf16* __restrict__ A, const bf16* __restrict__ Bt,
    const float* __restrict__ bias, const float* __restrict__ res,
    float* __restrict__ Cf, bf16* __restrict__ Cb,
    int N, int relu, float oscale) {
    hgemm_tile<K>(A, Bt, bias, res, Cf, Cb, N,
                  blockIdx.y * 128, blockIdx.x * 128, relu != 0, oscale);
}

__global__ void __launch_bounds__(256, 2) qkv_hgemm(
    const bf16* __restrict__ A, const bf16* __restrict__ Wt,
    const float* __restrict__ bq, const float* __restrict__ bk,
    const float* __restrict__ bv,
    bf16* __restrict__ q, bf16* __restrict__ k, bf16* __restrict__ v) {
    int z = blockIdx.z;
    int kind = z >> 2, h = z & 3;
    const bf16* Bt    = Wt + (size_t)z * D * D;
    const float* bias = (kind == 0 ? bq : kind == 1 ? bk : bv) + (size_t)h * D;
    bf16* C = (kind == 0 ? q : kind == 1 ? k : v) + (size_t)h * T * D;
    // round-12 numerics: q pre-scaled by 1/16, softmax uses __expf
    float oscale = (kind == 0) ? 0.0625f : 1.0f;
    hgemm_tile<D>(A, Bt, bias, nullptr, nullptr, C, D,
                  blockIdx.y * 128, blockIdx.x * 128, false, oscale);
}

// ===== HMMA flash attention: BQ=64, 4 warps, KV=32/stage, 2 CTAs/SM ==========
// (round-12 exact: single barrier per iteration, __expf softmax)
#define APITCH 264
#define KVR    32
#define KVSTG  (KVR * APITCH * 2)                 // 16896 B per K (or V) stage
#define ATTN_DSMEM ((64 + 4 * KVR) * APITCH * 2)  // 101376 B

__device__ __forceinline__ void cp_kv32(uint32_t kdst, uint32_t vdst,
                                        const bf16* __restrict__ kg,
                                        const bf16* __restrict__ vg, int tid) {
    #pragma unroll
    for (int t = 0; t < 8; t++) {
        int u = tid + t * 128;
        int row = u >> 5, c16 = u & 31;
        uint32_t so = (uint32_t)(row * (APITCH * 2) + c16 * 16);
        size_t go = (size_t)row * D + c16 * 8;
        cp16(kdst + so, kg + go);
        cp16(vdst + so, vg + go);
    }
}

__global__ void __launch_bounds__(128, 2) attn_kernel(
    const bf16* __restrict__ qg, const bf16* __restrict__ kg,
    const bf16* __restrict__ vg, bf16* __restrict__ cat) {

    extern __shared__ __align__(16) char dsm[];
    bf16* Qs = (bf16*)dsm;
    uint32_t qb32 = smem_u32(Qs);
    uint32_t kv0  = qb32 + 64 * APITCH * 2;

    int tid  = threadIdx.x;
    int w    = tid >> 5;
    int lane = tid & 31;
    int g    = lane >> 2;
    int j    = lane & 3;

    int b  = blockIdx.y >> 2, h = blockIdx.y & 3;
    int q0 = blockIdx.x * 64;

    const bf16* Qg  = qg + ((size_t)h * T + (size_t)b * SEQ + q0) * D;
    const bf16* Kg0 = kg + ((size_t)h * T + (size_t)b * SEQ) * D;
    const bf16* Vg0 = vg + ((size_t)h * T + (size_t)b * SEQ) * D;

    cp_kv32(kv0, kv0 + KVSTG, Kg0, Vg0, tid);
    CP_COMMIT();

    #pragma unroll
    for (int t = 0; t < 16; t++) {
        int u   = tid + t * 128;
        int row = u >> 5, c16 = u & 31;
        *(uint4*)(Qs + row * APITCH + c16 * 8) =
            *(const uint4*)(Qg + (size_t)row * D + c16 * 8);
    }

    float oacc[32][4];
    #pragma unroll
    for (int n = 0; n < 32; n++)
        #pragma unroll
        for (int c = 0; c < 4; c++) oacc[n][c] = 0.f;
    float la0 = 0.f, la1 = 0.f;

    int mi = lane >> 3;
    int l7 = lane & 7;
    uint32_t q_base = qb32 + (uint32_t)(((16 * w + (mi & 1) * 8 + l7) * APITCH + (mi >> 1) * 8) * 2);
    uint32_t k_off  = (uint32_t)((((mi >> 1) * 8 + l7) * APITCH + (mi & 1) * 8) * 2);
    uint32_t v_off  = (uint32_t)((((mi & 1) * 8 + l7) * APITCH + (mi >> 1) * 8) * 2);

    for (int it = 0; it < 64; it++) {
        CP_WAIT(0);
        __syncthreads();

        if (it + 1 < 64) {
            uint32_t st = kv0 + (uint32_t)((it + 1) & 1) * (2 * KVSTG);
            cp_kv32(st, st + KVSTG,
                    Kg0 + (size_t)(it + 1) * KVR * D,
                    Vg0 + (size_t)(it + 1) * KVR * D, tid);
            CP_COMMIT();
        }

        uint32_t kb = kv0 + (uint32_t)(it & 1) * (2 * KVSTG);
        uint32_t vb = kb + KVSTG;

        float sacc[4][4];
        #pragma unroll
        for (int n = 0; n < 4; n++)
            #pragma unroll
            for (int c = 0; c < 4; c++) sacc[n][c] = 0.f;

        #pragma unroll
        for (int kk = 0; kk < 16; kk++) {
            uint32_t eoff = (uint32_t)(kk * 32);
            uint32_t a[4];
            ldsm4(a, q_base + eoff);
            #pragma unroll
            for (int nt = 0; nt < 4; nt += 2) {
                uint32_t bbr[4];
                ldsm4(bbr, kb + k_off + eoff + (uint32_t)(nt * 8 * APITCH * 2));
                hmma(sacc[nt],     a, bbr[0], bbr[1]);
                hmma(sacc[nt + 1], a, bbr[2], bbr[3]);
            }
        }

        uint32_t pf[2][4];
        #pragma unroll
        for (int nt = 0; nt < 4; nt++) {
            float p0 = __expf(fminf(sacc[nt][0], 80.f));
            float p1 = __expf(fminf(sacc[nt][1], 80.f));
            float p2 = __expf(fminf(sacc[nt][2], 80.f));
            float p3 = __expf(fminf(sacc[nt][3], 80.f));
            la0 += p0 + p1;
            la1 += p2 + p3;
            int kt = nt >> 1, sub = nt & 1;
            pf[kt][2 * sub + 0] = cvt_bf16x2(p1, p0);
            pf[kt][2 * sub + 1] = cvt_bf16x2(p3, p2);
        }

        #pragma unroll
        for (int kt = 0; kt < 2; kt++) {
            uint32_t vra = vb + v_off + (uint32_t)(kt * 16 * APITCH * 2);
            #pragma unroll
            for (int nt = 0; nt < 32; nt += 2) {
                uint32_t bbr[4];
                ldsm4t(bbr, vra + (uint32_t)(nt * 8 * 2));
                hmma(oacc[nt],     pf[kt], bbr[0], bbr[1]);
                hmma(oacc[nt + 1], pf[kt], bbr[2], bbr[3]);
            }
        }
    }

    la0 += __shfl_xor_sync(0xffffffffu, la0, 1);
    la0 += __shfl_xor_sync(0xffffffffu, la0, 2);
    la1 += __shfl_xor_sync(0xffffffffu, la1, 1);
    la1 += __shfl_xor_sync(0xffffffffu, la1, 2);
    float inv0 = 1.f / la0;
    float inv1 = 1.f / la1;

    int row_lo = q0 + 16 * w + g;
    bf16* o_lo = cat + ((size_t)(b * SEQ + row_lo)) * (H * D) + h * D;
    bf16* o_hi = o_lo + 8 * (size_t)(H * D);
    #pragma unroll
    for (int nt = 0; nt < 32; nt++) {
        *(uint32_t*)(o_lo + nt * 8 + 2 * j) =
            cvt_bf16x2(oacc[nt][1] * inv0, oacc[nt][0] * inv0);
        *(uint32_t*)(o_hi + nt * 8 + 2 * j) =
            cvt_bf16x2(oacc[nt][3] * inv1, oacc[nt][2] * inv1);
    }
}

// ---------------- launch --------------------------------------------------
extern "C" void kernel_launch(void* const* d_in, const int* in_sizes, int n_in,
                              void* d_out, int out_size) {
    const float* x   = (const float*)d_in[0];
    const float* Wq  = (const float*)d_in[1];
    const float* bq  = (const float*)d_in[2];
    const float* Wk  = (const float*)d_in[3];
    const float* bk  = (const float*)d_in[4];
    const float* Wv  = (const float*)d_in[5];
    const float* bv  = (const float*)d_in[6];
    const float* Wo  = (const float*)d_in[7];
    const float* bo  = (const float*)d_in[8];
    const float* g1  = (const float*)d_in[9];
    const float* be1 = (const float*)d_in[10];
    const float* g2  = (const float*)d_in[11];
    const float* be2 = (const float*)d_in[12];
    const float* W1  = (const float*)d_in[13];
    const float* bf1 = (const float*)d_in[14];
    const float* W2  = (const float*)d_in[15];
    const float* bf2 = (const float*)d_in[16];
    float* out = (float*)d_out;

    bf16 *xnb, *qb, *kb, *vb, *catb, *xn2b, *ffb, *wtqkv, *wto, *wt1, *wt2;
    float *x1;
    cudaGetSymbolAddress((void**)&xnb,   g_xnb);
    cudaGetSymbolAddress((void**)&qb,    g_qb);
    cudaGetSymbolAddress((void**)&kb,    g_kb);
    cudaGetSymbolAddress((void**)&vb,    g_vb);
    cudaGetSymbolAddress((void**)&catb,  g_catb);
    cudaGetSymbolAddress((void**)&x1,    g_x1);
    cudaGetSymbolAddress((void**)&xn2b,  g_xn2b);
    cudaGetSymbolAddress((void**)&ffb,   g_ffb);
    cudaGetSymbolAddress((void**)&wtqkv, g_wtqkv);
    cudaGetSymbolAddress((void**)&wto,   g_wto);
    cudaGetSymbolAddress((void**)&wt1,   g_wt1);
    cudaGetSymbolAddress((void**)&wt2,   g_wt2);

    cudaFuncSetAttribute(attn_kernel, cudaFuncAttributeMaxDynamicSharedMemorySize,
                         ATTN_DSMEM);
    cudaFuncSetAttribute(hgemm_kernel<1024>, cudaFuncAttributeMaxDynamicSharedMemorySize,
                         HGEMM_DSMEM);
    cudaFuncSetAttribute(hgemm_kernel<512>, cudaFuncAttributeMaxDynamicSharedMemorySize,
                         HGEMM_DSMEM);
    cudaFuncSetAttribute(hgemm_kernel<256>, cudaFuncAttributeMaxDynamicSharedMemorySize,
                         HGEMM_DSMEM);
    cudaFuncSetAttribute(qkv_hgemm, cudaFuncAttributeMaxDynamicSharedMemorySize,
                         HGEMM_DSMEM);

    // 0) weight convert+transpose + LN1, single launch
    prolog_kernel<<<1280 + T / 8, 256>>>(Wq, Wk, Wv, Wo, W1, W2,
                                         wtqkv, wto, wt1, wt2,
                                         x, g1, be1, xnb);
    // 1) QKV projections (HMMA 3-stage 1-sync, 2 CTAs/SM, q pre-scaled by 1/16)
    qkv_hgemm<<<dim3(2, 128, 12), 256, HGEMM_DSMEM>>>(xnb, wtqkv, bq, bk, bv, qb, kb, vb);
    // 2) HMMA flash attention (round-12 exact) -> concat bf16
    attn_kernel<<<dim3(32, 32), 128, ATTN_DSMEM>>>(qb, kb, vb, catb);
    // 3) output projection + residual (fp32 out)
    hgemm_kernel<1024><<<dim3(2, 128), 256, HGEMM_DSMEM>>>(catb, wto, bo, x, x1, nullptr,
                                                           D, 0, 1.0f);
    // 4) LN2 -> bf16
    ln_kernel<<<T / 8, 256>>>(x1, g2, be2, xn2b);
    // 5) FFN up + relu -> bf16
    hgemm_kernel<256><<<dim3(4, 128), 256, HGEMM_DSMEM>>>(xn2b, wt1, bf1, nullptr, nullptr, ffb,
                                                          F, 1, 1.0f);
    // 6) FFN down + residual -> output fp32
    hgemm_kernel<512><<<dim3(2, 128), 256, HGEMM_DSMEM>>>(ffb, wt2, bf2, x1, out, nullptr,
                                                          D, 0, 1.0f);
}